// round 6
// baseline (speedup 1.0000x reference)
#include <cuda_runtime.h>
#include <cuda_bf16.h>
#include <cstdint>

// Problem constants
#define Bsz   128
#define Himg  28
#define Wimg  28
#define C     512
#define WS    7
#define NH    16
#define HD    32
#define NWIN  16            // windows per image: (28/7)*(28/7)
#define L     49            // WS*WS
#define NTOK  (Bsz*Himg*Wimg)        // 100352 tokens
#define NWH   (Bsz*NWIN*NH)          // 32768 window-heads
#define QSCALE 0.17677669529663687f  // 1/sqrt(32)

// ---------------- scratch (device globals; no allocation allowed) ----------
// NOTE: device globals are ONLY ever referenced from device code. Passing
// them as host-side kernel arguments passes the host shadow symbol (garbage
// pointer) — that was the round-0..5 bug.
__device__ float g_q [Bsz*NWIN*NH*L*HD];   // [(win*16+head)][l][d]
__device__ float g_k [Bsz*NWIN*NH*L*HD];
__device__ float g_v [Bsz*NWIN*NH*L*HD];
__device__ float g_ao[(size_t)NTOK*C];     // attention out, token-major

// ======================= Kernel 1: QKV GEMM + window scatter ===============
// A [100352,512] x B [512,1536] + bias -> scatter into g_q/g_k/g_v
#define BM 128
#define BN 128
#define BK 16
__global__ __launch_bounds__(256) void qkv_gemm_kernel(
    const float* __restrict__ A, const float* __restrict__ Bmat,
    const float* __restrict__ bias)
{
    __shared__ float As[BK][BM];
    __shared__ float Bs[BK][BN];

    const int bm = blockIdx.y * BM;
    const int bn = blockIdx.x * BN;
    const int tid = threadIdx.x;
    const int tx = tid & 15;      // 16 cols of threads
    const int ty = tid >> 4;      // 16 rows of threads

    float acc[8][8];
    #pragma unroll
    for (int i = 0; i < 8; i++)
        #pragma unroll
        for (int j = 0; j < 8; j++) acc[i][j] = 0.f;

    for (int k0 = 0; k0 < 512; k0 += BK) {
        // load A tile (128x16) as float4, store transposed
        #pragma unroll
        for (int it = 0; it < 2; it++) {
            int f = tid + it * 256;          // 512 float4s
            int r = f >> 2, c4 = (f & 3) << 2;
            float4 a = *(const float4*)(A + (size_t)(bm + r) * 512 + k0 + c4);
            As[c4 + 0][r] = a.x; As[c4 + 1][r] = a.y;
            As[c4 + 2][r] = a.z; As[c4 + 3][r] = a.w;
        }
        // load B tile (16x128)
        #pragma unroll
        for (int it = 0; it < 2; it++) {
            int f = tid + it * 256;
            int r = f >> 5, c4 = (f & 31) << 2;
            *(float4*)&Bs[r][c4] = *(const float4*)(Bmat + (size_t)(k0 + r) * 1536 + bn + c4);
        }
        __syncthreads();

        #pragma unroll
        for (int k = 0; k < BK; k++) {
            float ra[8], rb[8];
            #pragma unroll
            for (int i = 0; i < 8; i++) ra[i] = As[k][ty * 8 + i];
            #pragma unroll
            for (int j = 0; j < 8; j++) rb[j] = Bs[k][tx * 8 + j];
            #pragma unroll
            for (int i = 0; i < 8; i++)
                #pragma unroll
                for (int j = 0; j < 8; j++) acc[i][j] = fmaf(ra[i], rb[j], acc[i][j]);
        }
        __syncthreads();
    }

    // epilogue: fused window partition scatter
    #pragma unroll
    for (int i = 0; i < 8; i++) {
        int m = bm + ty * 8 + i;
        int b = m / 784, p = m % 784;
        int h = p / 28, w = p % 28;
        int win = b * NWIN + (h / 7) * 4 + (w / 7);
        int l = (h % 7) * 7 + (w % 7);
        #pragma unroll
        for (int j = 0; j < 8; j++) {
            int n = bn + tx * 8 + j;
            float val = acc[i][j] + bias[n];
            int s    = n >> 9;       // 0=q 1=k 2=v
            int rem  = n & 511;
            int head = rem >> 5;
            int d    = rem & 31;
            size_t dst = (((size_t)(win * NH + head)) * L + l) * HD + d;
            if (s == 0)      g_q[dst] = val * QSCALE;
            else if (s == 1) g_k[dst] = val;
            else             g_v[dst] = val;
        }
    }
}

// ======================= Kernel 2: windowed attention =======================
// one block per (window, head); fused bias gather + mask + softmax + AV +
// window-reverse scatter into token-major g_ao.
__global__ __launch_bounds__(256) void attn_kernel(
    const float* __restrict__ mask,
    const float* __restrict__ bias_table,
    const int*   __restrict__ rel_index)
{
    const int wh     = blockIdx.x;      // win*16 + head
    const int head   = wh & 15;
    const int window = wh >> 4;
    const int winImg = window & (NWIN - 1);
    const int tid    = threadIdx.x;

    __shared__ float qs[L][HD + 1];
    __shared__ float ks[L][HD + 1];
    __shared__ float vs[L][HD + 1];
    __shared__ float sc[L][L + 1];

    const float* qp = g_q + (size_t)wh * L * HD;
    const float* kp = g_k + (size_t)wh * L * HD;
    const float* vp = g_v + (size_t)wh * L * HD;

    for (int f = tid; f < L * HD; f += 256) {
        int r = f >> 5, d = f & 31;
        qs[r][d] = qp[f];
        ks[r][d] = kp[f];
        vs[r][d] = vp[f];
    }
    __syncthreads();

    // scores + relative-position bias + shift mask
    for (int idx = tid; idx < L * L; idx += 256) {
        int qi = idx / L, ki = idx - qi * L;
        float dot = 0.f;
        #pragma unroll
        for (int d = 0; d < HD; d++) dot = fmaf(qs[qi][d], ks[ki][d], dot);
        dot += bias_table[rel_index[idx] * NH + head];
        dot += mask[winImg * (L * L) + idx];
        sc[qi][ki] = dot;
    }
    __syncthreads();

    // softmax per row (one warp per row, strided)
    const int warp = tid >> 5, lane = tid & 31;
    for (int qi = warp; qi < L; qi += 8) {
        float mx = -1e30f;
        for (int ki = lane; ki < L; ki += 32) mx = fmaxf(mx, sc[qi][ki]);
        #pragma unroll
        for (int o = 16; o > 0; o >>= 1) mx = fmaxf(mx, __shfl_xor_sync(0xffffffffu, mx, o));
        float sum = 0.f;
        for (int ki = lane; ki < L; ki += 32) {
            float e = __expf(sc[qi][ki] - mx);
            sc[qi][ki] = e;
            sum += e;
        }
        #pragma unroll
        for (int o = 16; o > 0; o >>= 1) sum += __shfl_xor_sync(0xffffffffu, sum, o);
        float inv = __frcp_rn(sum);
        for (int ki = lane; ki < L; ki += 32) sc[qi][ki] *= inv;
    }
    __syncthreads();

    // out = attn @ v, scatter to token layout (window reverse)
    const int b  = window >> 4;
    const int wi = window & 15;
    for (int idx = tid; idx < L * HD; idx += 256) {
        int qi = idx >> 5, d = idx & 31;
        float a = 0.f;
        #pragma unroll
        for (int ki = 0; ki < L; ki++) a = fmaf(sc[qi][ki], vs[ki][d], a);
        int h = (wi >> 2) * 7 + qi / 7;
        int w = (wi & 3) * 7 + qi % 7;
        size_t tok = (size_t)b * 784 + h * 28 + w;
        g_ao[tok * C + head * HD + d] = a;
    }
}

// ======================= Kernel 3: output projection ========================
// A is the device-global g_ao (accessed directly from device code — NOT
// passed from host). out = g_ao @ w_proj + b_proj.
__global__ __launch_bounds__(256) void proj_gemm_kernel(
    const float* __restrict__ Bmat,
    const float* __restrict__ bias, float* __restrict__ out)
{
    __shared__ float As[BK][BM];
    __shared__ float Bs[BK][BN];

    const float* __restrict__ A = g_ao;   // device-side reference (valid)

    const int bm = blockIdx.y * BM;
    const int bn = blockIdx.x * BN;
    const int tid = threadIdx.x;
    const int tx = tid & 15;
    const int ty = tid >> 4;

    float acc[8][8];
    #pragma unroll
    for (int i = 0; i < 8; i++)
        #pragma unroll
        for (int j = 0; j < 8; j++) acc[i][j] = 0.f;

    for (int k0 = 0; k0 < 512; k0 += BK) {
        #pragma unroll
        for (int it = 0; it < 2; it++) {
            int f = tid + it * 256;
            int r = f >> 2, c4 = (f & 3) << 2;
            float4 a = *(const float4*)(A + (size_t)(bm + r) * 512 + k0 + c4);
            As[c4 + 0][r] = a.x; As[c4 + 1][r] = a.y;
            As[c4 + 2][r] = a.z; As[c4 + 3][r] = a.w;
        }
        #pragma unroll
        for (int it = 0; it < 2; it++) {
            int f = tid + it * 256;
            int r = f >> 5, c4 = (f & 31) << 2;
            *(float4*)&Bs[r][c4] = *(const float4*)(Bmat + (size_t)(k0 + r) * 512 + bn + c4);
        }
        __syncthreads();

        #pragma unroll
        for (int k = 0; k < BK; k++) {
            float ra[8], rb[8];
            #pragma unroll
            for (int i = 0; i < 8; i++) ra[i] = As[k][ty * 8 + i];
            #pragma unroll
            for (int j = 0; j < 8; j++) rb[j] = Bs[k][tx * 8 + j];
            #pragma unroll
            for (int i = 0; i < 8; i++)
                #pragma unroll
                for (int j = 0; j < 8; j++) acc[i][j] = fmaf(ra[i], rb[j], acc[i][j]);
        }
        __syncthreads();
    }

    #pragma unroll
    for (int i = 0; i < 8; i++) {
        size_t m = bm + ty * 8 + i;
        #pragma unroll
        for (int j = 0; j < 8; j += 4) {
            int n = bn + tx * 8 + j;
            float4 o;
            o.x = acc[i][j + 0] + bias[n + 0];
            o.y = acc[i][j + 1] + bias[n + 1];
            o.z = acc[i][j + 2] + bias[n + 2];
            o.w = acc[i][j + 3] + bias[n + 3];
            *(float4*)(out + m * 512 + n) = o;
        }
    }
}

// =========================== launch ========================================
extern "C" void kernel_launch(void* const* d_in, const int* in_sizes, int n_in,
                              void* d_out, int out_size)
{
    // Bind inputs by DESCENDING SIZE RANK — invariant to input ordering and
    // to whether in_sizes is elements or bytes (ranking identical either way):
    //   rank 0: x          (51380224 elem)
    //   rank 1: w_qkv      (786432)
    //   rank 2: w_proj     (262144)
    //   rank 3: mask       (38416)
    //   rank 4: bias_table (2704)
    //   rank 5: rel_index  (2401)   [int32]
    //   rank 6: b_qkv      (1536)
    //   rank 7: b_proj     (512)
    //   (height/width, size 1 — unused)
    int order[16];
    int m = n_in > 16 ? 16 : n_in;
    for (int i = 0; i < m; i++) order[i] = i;
    for (int a = 0; a < m; a++) {
        int best = a;
        for (int b2 = a + 1; b2 < m; b2++)
            if ((unsigned)in_sizes[order[b2]] > (unsigned)in_sizes[order[best]])
                best = b2;
        int t = order[a]; order[a] = order[best]; order[best] = t;
    }

    const float* x          = (const float*)d_in[order[0]];
    const float* w_qkv      = (const float*)d_in[order[1]];
    const float* w_proj     = (const float*)d_in[order[2]];
    const float* mask       = (const float*)d_in[order[3]];
    const float* bias_table = (const float*)d_in[order[4]];
    const int*   rel_index  = (const int*)  d_in[order[5]];
    const float* b_qkv      = (const float*)d_in[order[6]];
    const float* b_proj     = (const float*)d_in[order[7]];

    float* out = (float*)d_out;

    // 1) QKV projection + window partition: grid (1536/128, 100352/128)
    qkv_gemm_kernel<<<dim3(12, 784), 256>>>(x, w_qkv, b_qkv);

    // 2) per-(window, head) attention
    attn_kernel<<<NWH, 256>>>(mask, bias_table, rel_index);

    // 3) output projection: grid (512/128, 100352/128)
    proj_gemm_kernel<<<dim3(4, 784), 256>>>(w_proj, b_proj, out);
}

// round 8
// speedup vs baseline: 2.1247x; 2.1247x over previous
#include <cuda_runtime.h>
#include <cuda_bf16.h>
#include <cstdint>

// Problem constants
#define Bsz   128
#define Himg  28
#define Wimg  28
#define C     512
#define WS    7
#define NH    16
#define HD    32
#define NWIN  16
#define L     49
#define NTOK  (Bsz*Himg*Wimg)        // 100352
#define NWH   (Bsz*NWIN*NH)          // 32768
#define QSCALE 0.17677669529663687f

// ---------------- scratch (device globals; device-code access only) --------
__device__ float    g_q [Bsz*NWIN*NH*L*HD];
__device__ float    g_k [Bsz*NWIN*NH*L*HD];
__device__ float    g_v [Bsz*NWIN*NH*L*HD];
__device__ float    g_ao[(size_t)NTOK*C];
__device__ uint32_t g_wqkvT[1536*512];   // w_qkv^T as tf32 bits [N=1536][K=512]
__device__ uint32_t g_wprojT[512*512];   // w_proj^T as tf32 bits [N=512][K=512]

__device__ __forceinline__ uint32_t f2tf32(float f) {
    uint32_t u; asm("cvt.rna.tf32.f32 %0, %1;" : "=r"(u) : "f"(f)); return u;
}

// m16n8k8 tf32 mma (arch-agnostic PTX; compiles on plain sm_103 target)
__device__ __forceinline__ void mma_tf32(float* c, const uint32_t* a, const uint32_t* b) {
    asm volatile(
        "mma.sync.aligned.m16n8k8.row.col.f32.tf32.tf32.f32 "
        "{%0,%1,%2,%3}, {%4,%5,%6,%7}, {%8,%9}, {%0,%1,%2,%3};\n"
        : "+f"(c[0]), "+f"(c[1]), "+f"(c[2]), "+f"(c[3])
        : "r"(a[0]), "r"(a[1]), "r"(a[2]), "r"(a[3]), "r"(b[0]), "r"(b[1]));
}

// ======================= transpose + cvt (tiny) ============================
__global__ void transpose_cvt_kernel(const float* __restrict__ src, int R, int Ccols, int mode)
{
    __shared__ uint32_t t[32][33];
    uint32_t* dst = mode ? g_wprojT : g_wqkvT;
    int bx = blockIdx.x * 32, by = blockIdx.y * 32;
    int tx = threadIdx.x, ty = threadIdx.y;
    #pragma unroll
    for (int i = 0; i < 32; i += 8)
        t[ty + i][tx] = f2tf32(src[(size_t)(by + ty + i) * Ccols + bx + tx]);
    __syncthreads();
    #pragma unroll
    for (int i = 0; i < 32; i += 8)
        dst[(size_t)(bx + ty + i) * R + by + tx] = t[tx][ty + i];
}

// ======================= tf32 mma.sync GEMM (QKV / proj) ===================
// D tile [128,128] = A[128x512] @ B^T (B^T rows = output cols, K-major).
// mode 0: A=x,    B=g_wqkvT,  fused window-partition scatter (+bias, q scale)
// mode 1: A=g_ao, B=g_wprojT, write to out (+bias)
#define BK    32
#define SPAD  36   // smem row stride in words: banks (4r+c)&31 all distinct

__global__ __launch_bounds__(256) void gemm_mma_kernel(
    const float* __restrict__ A_ext, const float* __restrict__ bias,
    float* __restrict__ outp, int mode)
{
    __shared__ uint32_t As[128][SPAD];
    __shared__ uint32_t Bs[128][SPAD];

    const int tid  = threadIdx.x;
    const int wid  = tid >> 5, lane = tid & 31;
    const int warp_m = wid & 1;          // 2 warps over M
    const int warp_n = wid >> 1;         // 4 warps over N
    const int bm = blockIdx.y * 128;
    const int bn = blockIdx.x * 128;
    const int grp = lane >> 2, thr = lane & 3;

    const float*    A  = (mode == 0) ? A_ext : g_ao;
    const uint32_t* BT = (mode == 0) ? g_wqkvT : g_wprojT;

    float c[4][4][4];
    #pragma unroll
    for (int mt = 0; mt < 4; mt++)
        #pragma unroll
        for (int nt = 0; nt < 4; nt++)
            #pragma unroll
            for (int e = 0; e < 4; e++) c[mt][nt][e] = 0.f;

    const int lrow = tid >> 3;            // 0..31 (row group for loads)
    const int lc4  = (tid & 7) << 2;      // 0..28 step 4

    for (int k0 = 0; k0 < 512; k0 += BK) {
        // stage A (cvt to tf32) and B tiles: 128 rows x 32 cols each
        #pragma unroll
        for (int it = 0; it < 4; it++) {
            int row = lrow + it * 32;
            float4 av = *(const float4*)(A + (size_t)(bm + row) * 512 + k0 + lc4);
            uint4 aw;
            aw.x = f2tf32(av.x); aw.y = f2tf32(av.y);
            aw.z = f2tf32(av.z); aw.w = f2tf32(av.w);
            *(uint4*)&As[row][lc4] = aw;
            uint4 bw = *(const uint4*)(BT + (size_t)(bn + row) * 512 + k0 + lc4);
            *(uint4*)&Bs[row][lc4] = bw;
        }
        __syncthreads();

        #pragma unroll
        for (int kk = 0; kk < BK; kk += 8) {
            uint32_t af[4][4], bf[4][2];
            #pragma unroll
            for (int mt = 0; mt < 4; mt++) {
                int r = warp_m * 64 + mt * 16 + grp;
                af[mt][0] = As[r][kk + thr];
                af[mt][1] = As[r + 8][kk + thr];
                af[mt][2] = As[r][kk + thr + 4];
                af[mt][3] = As[r + 8][kk + thr + 4];
            }
            #pragma unroll
            for (int nt = 0; nt < 4; nt++) {
                int nn = warp_n * 32 + nt * 8 + grp;
                bf[nt][0] = Bs[nn][kk + thr];
                bf[nt][1] = Bs[nn][kk + thr + 4];
            }
            #pragma unroll
            for (int mt = 0; mt < 4; mt++)
                #pragma unroll
                for (int nt = 0; nt < 4; nt++)
                    mma_tf32(c[mt][nt], af[mt], bf[nt]);
        }
        __syncthreads();
    }

    // ---- epilogue ----
    // cols: n = bn + warp_n*32 + nt*8 + 2*thr (+0/+1). head/s constant per warp.
    if (mode == 0) {
        const int nwbase = bn + warp_n * 32;           // 32-aligned
        const int s      = nwbase >> 9;                // 0=q 1=k 2=v (block 128-aligned in 512 seg)
        const int head   = (nwbase & 511) >> 5;        // constant per warp
        float* basep = (s == 0) ? g_q : ((s == 1) ? g_k : g_v);
        const float scl = (s == 0) ? QSCALE : 1.0f;
        #pragma unroll
        for (int mt = 0; mt < 4; mt++) {
            #pragma unroll
            for (int half = 0; half < 2; half++) {
                int m = bm + warp_m * 64 + mt * 16 + grp + half * 8;
                int b = m / 784, p = m % 784;
                int h = p / 28, w = p % 28;
                int win  = b * NWIN + (h / 7) * 4 + (w / 7);
                int lpos = (h % 7) * 7 + (w % 7);
                float* dst = basep + (((size_t)(win * NH + head)) * L + lpos) * HD;
                #pragma unroll
                for (int nt = 0; nt < 4; nt++) {
                    int n = nwbase + nt * 8 + 2 * thr;
                    int d = n & 31;
                    float2 o;
                    o.x = (c[mt][nt][half * 2 + 0] + bias[n + 0]) * scl;
                    o.y = (c[mt][nt][half * 2 + 1] + bias[n + 1]) * scl;
                    *(float2*)(dst + d) = o;
                }
            }
        }
    } else {
        #pragma unroll
        for (int mt = 0; mt < 4; mt++) {
            #pragma unroll
            for (int half = 0; half < 2; half++) {
                size_t m = bm + warp_m * 64 + mt * 16 + grp + half * 8;
                #pragma unroll
                for (int nt = 0; nt < 4; nt++) {
                    int n = bn + warp_n * 32 + nt * 8 + 2 * thr;
                    float2 o;
                    o.x = c[mt][nt][half * 2 + 0] + bias[n + 0];
                    o.y = c[mt][nt][half * 2 + 1] + bias[n + 1];
                    *(float2*)(outp + m * 512 + n) = o;
                }
            }
        }
    }
}

// ======================= windowed attention (unchanged) ====================
__global__ __launch_bounds__(256) void attn_kernel(
    const float* __restrict__ mask,
    const float* __restrict__ bias_table,
    const int*   __restrict__ rel_index)
{
    const int wh     = blockIdx.x;
    const int head   = wh & 15;
    const int window = wh >> 4;
    const int winImg = window & (NWIN - 1);
    const int tid    = threadIdx.x;

    __shared__ float qs[L][HD + 1];
    __shared__ float ks[L][HD + 1];
    __shared__ float vs[L][HD + 1];
    __shared__ float sc[L][L + 1];

    const float* qp = g_q + (size_t)wh * L * HD;
    const float* kp = g_k + (size_t)wh * L * HD;
    const float* vp = g_v + (size_t)wh * L * HD;

    for (int f = tid; f < L * HD; f += 256) {
        int r = f >> 5, d = f & 31;
        qs[r][d] = qp[f];
        ks[r][d] = kp[f];
        vs[r][d] = vp[f];
    }
    __syncthreads();

    for (int idx = tid; idx < L * L; idx += 256) {
        int qi = idx / L, ki = idx - qi * L;
        float dot = 0.f;
        #pragma unroll
        for (int d = 0; d < HD; d++) dot = fmaf(qs[qi][d], ks[ki][d], dot);
        dot += bias_table[rel_index[idx] * NH + head];
        dot += mask[winImg * (L * L) + idx];
        sc[qi][ki] = dot;
    }
    __syncthreads();

    const int warp = tid >> 5, lane = tid & 31;
    for (int qi = warp; qi < L; qi += 8) {
        float mx = -1e30f;
        for (int ki = lane; ki < L; ki += 32) mx = fmaxf(mx, sc[qi][ki]);
        #pragma unroll
        for (int o = 16; o > 0; o >>= 1) mx = fmaxf(mx, __shfl_xor_sync(0xffffffffu, mx, o));
        float sum = 0.f;
        for (int ki = lane; ki < L; ki += 32) {
            float e = __expf(sc[qi][ki] - mx);
            sc[qi][ki] = e;
            sum += e;
        }
        #pragma unroll
        for (int o = 16; o > 0; o >>= 1) sum += __shfl_xor_sync(0xffffffffu, sum, o);
        float inv = __frcp_rn(sum);
        for (int ki = lane; ki < L; ki += 32) sc[qi][ki] *= inv;
    }
    __syncthreads();

    const int b  = window >> 4;
    const int wi = window & 15;
    for (int idx = tid; idx < L * HD; idx += 256) {
        int qi = idx >> 5, d = idx & 31;
        float a = 0.f;
        #pragma unroll
        for (int ki = 0; ki < L; ki++) a = fmaf(sc[qi][ki], vs[ki][d], a);
        int h = (wi >> 2) * 7 + qi / 7;
        int w = (wi & 3) * 7 + qi % 7;
        size_t tok = (size_t)b * 784 + h * 28 + w;
        g_ao[tok * C + head * HD + d] = a;
    }
}

// =========================== launch ========================================
extern "C" void kernel_launch(void* const* d_in, const int* in_sizes, int n_in,
                              void* d_out, int out_size)
{
    // Bind by descending size rank (order/unit invariant)
    int order[16];
    int m = n_in > 16 ? 16 : n_in;
    for (int i = 0; i < m; i++) order[i] = i;
    for (int a = 0; a < m; a++) {
        int best = a;
        for (int b2 = a + 1; b2 < m; b2++)
            if ((unsigned)in_sizes[order[b2]] > (unsigned)in_sizes[order[best]])
                best = b2;
        int t = order[a]; order[a] = order[best]; order[best] = t;
    }
    const float* x          = (const float*)d_in[order[0]];
    const float* w_qkv      = (const float*)d_in[order[1]];
    const float* w_proj     = (const float*)d_in[order[2]];
    const float* mask       = (const float*)d_in[order[3]];
    const float* bias_table = (const float*)d_in[order[4]];
    const int*   rel_index  = (const int*)  d_in[order[5]];
    const float* b_qkv      = (const float*)d_in[order[6]];
    const float* b_proj     = (const float*)d_in[order[7]];
    float* out = (float*)d_out;

    // 0) weight transposes (+tf32 cvt), tiny
    transpose_cvt_kernel<<<dim3(48, 16), dim3(32, 8)>>>(w_qkv, 512, 1536, 0);
    transpose_cvt_kernel<<<dim3(16, 16), dim3(32, 8)>>>(w_proj, 512, 512, 1);

    // 1) QKV projection (tensor cores) + window scatter
    gemm_mma_kernel<<<dim3(12, 784), 256>>>(x, b_qkv, nullptr, 0);

    // 2) per-(window, head) attention
    attn_kernel<<<NWH, 256>>>(mask, bias_table, rel_index);

    // 3) output projection (tensor cores)
    gemm_mma_kernel<<<dim3(4, 784), 256>>>(nullptr, b_proj, out, 1);
}